// round 1
// baseline (speedup 1.0000x reference)
#include <cuda_runtime.h>

// SSIM (8x8 box-sum variant, VALID padding) over (32,3,512,512) fp32 pairs,
// output = scalar mean(1 - ssim_map).
//
// Structure: per CTA = one image-channel x 256 output columns x ~85 output rows.
// Horizontal 8-sums from a double-buffered shared row; vertical 8-sums via a
// register ring buffer (static indices via 8x unroll). Scalar result reduced
// via warp shuffles + one double atomicAdd per CTA into a __device__ global.

#define FULLMASK 0xFFFFFFFFu

constexpr int W       = 512;
constexpr int OW      = 505;           // 512 - 8 + 1
constexpr int OH      = 505;
constexpr int NIMG    = 96;            // 32 * 3
constexpr int THREADS = 128;
constexpr int CPT     = 2;             // output cols per thread
constexpr int TILE_OC = THREADS * CPT; // 256
constexpr int TILE_IC = TILE_OC + 7;   // 263
constexpr int SMC     = 264;           // padded row width (even, 8B-aligned float2)
constexpr int OB      = 85;            // output rows per band
constexpr int NB      = 6;             // 6*85 = 510 >= 505
constexpr float C1f   = 1.0e-4f;       // (0.01*1)^2
constexpr float C2f   = 9.0e-4f;       // (0.03*1)^2

__device__ double g_acc;

__global__ void zero_acc_kernel() { g_acc = 0.0; }

__global__ void finalize_kernel(float* out) {
    out[0] = (float)(g_acc / 24482400.0);   // 96 * 505 * 505
}

__global__ __launch_bounds__(THREADS) void ssim_kernel(
    const float* __restrict__ A, const float* __restrict__ B)
{
    __shared__ __align__(16) float sma[2][SMC];
    __shared__ __align__(16) float smb[2][SMC];
    __shared__ float wsum[THREADS / 32];

    const int t    = threadIdx.x;
    const int x0   = blockIdx.x * TILE_OC;
    const int band = blockIdx.y;
    const int img  = blockIdx.z;

    const int y0       = band * OB;
    const int band_out = min(OB, OH - y0);
    const int band_in  = band_out + 7;

    const size_t base = (size_t)img * (size_t)(W * W);
    const float* Ai = A + base;
    const float* Bi = B + base;

    // Vertical sliding-window state (per owned output column).
    float ring[CPT][5][8];
    float V[CPT][5];
#pragma unroll
    for (int j = 0; j < CPT; ++j) {
#pragma unroll
        for (int q = 0; q < 5; ++q) {
            V[j][q] = 0.0f;
#pragma unroll
            for (int p = 0; p < 8; ++p) ring[j][q][p] = 0.0f;
        }
    }

    float acc = 0.0f;

    // Load lanes: each thread fills up to 3 columns of the 263-wide input row.
    const int lc0 = t, lc1 = t + 128, lc2 = t + 256;
    const int gc0 = x0 + lc0, gc1 = x0 + lc1, gc2 = x0 + lc2;
    const bool has2 = (lc2 < TILE_IC);
    const bool v0 = (gc0 < W);
    const bool v1 = (gc1 < W);
    const bool v2 = has2 && (gc2 < W);

    // Preload row 0 into buffer 0.
    {
        const float* ra = Ai + (size_t)y0 * W;
        const float* rb = Bi + (size_t)y0 * W;
        sma[0][lc0] = v0 ? ra[gc0] : 0.0f;
        smb[0][lc0] = v0 ? rb[gc0] : 0.0f;
        sma[0][lc1] = v1 ? ra[gc1] : 0.0f;
        smb[0][lc1] = v1 ? rb[gc1] : 0.0f;
        if (has2) {
            sma[0][lc2] = v2 ? ra[gc2] : 0.0f;
            smb[0][lc2] = v2 ? rb[gc2] : 0.0f;
        }
    }
    __syncthreads();

    const int iters = (band_in + 7) & ~7;   // uniform trip count, 8x unroll
    for (int ib = 0; ib < iters; ib += 8) {
#pragma unroll
        for (int p = 0; p < 8; ++p) {
            const int i   = ib + p;
            const int cur = i & 1;

            // ---- prefetch row i+1 into registers (overlap DRAM latency) ----
            float pa0 = 0.f, pa1 = 0.f, pa2 = 0.f;
            float pb0 = 0.f, pb1 = 0.f, pb2 = 0.f;
            if (i + 1 < band_in) {
                const float* ra = Ai + (size_t)(y0 + i + 1) * W;
                const float* rb = Bi + (size_t)(y0 + i + 1) * W;
                if (v0) { pa0 = ra[gc0]; pb0 = rb[gc0]; }
                if (v1) { pa1 = ra[gc1]; pb1 = rb[gc1]; }
                if (v2) { pa2 = ra[gc2]; pb2 = rb[gc2]; }
            }

            // ---- horizontal 8-sums for this thread's 2 output columns ----
            const float2* fa = reinterpret_cast<const float2*>(sma[cur]) + t;
            const float2* fb = reinterpret_cast<const float2*>(smb[cur]) + t;
            float a[10], b[10];
            {
                float2 u;
                u = fa[0]; a[0] = u.x; a[1] = u.y;
                u = fa[1]; a[2] = u.x; a[3] = u.y;
                u = fa[2]; a[4] = u.x; a[5] = u.y;
                u = fa[3]; a[6] = u.x; a[7] = u.y;
                u = fa[4]; a[8] = u.x; a[9] = u.y;
                u = fb[0]; b[0] = u.x; b[1] = u.y;
                u = fb[1]; b[2] = u.x; b[3] = u.y;
                u = fb[2]; b[4] = u.x; b[5] = u.y;
                u = fb[3]; b[6] = u.x; b[7] = u.y;
                u = fb[4]; b[8] = u.x; b[9] = u.y;
            }

            float s1 = 0.f, s2 = 0.f, s11 = 0.f, s22 = 0.f, s12 = 0.f;
#pragma unroll
            for (int k = 0; k < 8; ++k) {
                const float av = a[k], bv = b[k];
                s1  += av;       s2  += bv;
                s11 += av * av;  s22 += bv * bv;
                s12 += av * bv;
            }
            float h[CPT][5];
            h[0][0] = s1; h[0][1] = s2; h[0][2] = s11; h[0][3] = s22; h[0][4] = s12;
            {
                const float a0 = a[0], b0 = b[0], a8 = a[8], b8 = b[8];
                h[1][0] = s1  - a0       + a8;
                h[1][1] = s2  - b0       + b8;
                h[1][2] = s11 - a0 * a0  + a8 * a8;
                h[1][3] = s22 - b0 * b0  + b8 * b8;
                h[1][4] = s12 - a0 * b0  + a8 * b8;
            }

            // ---- vertical sliding update (static ring index p) ----
#pragma unroll
            for (int j = 0; j < CPT; ++j)
#pragma unroll
                for (int q = 0; q < 5; ++q) {
                    const float hv = h[j][q];
                    V[j][q] += hv - ring[j][q][p];
                    ring[j][q][p] = hv;
                }

            // ---- SSIM for completed windows ----
            if (i >= 7 && i < band_in) {
#pragma unroll
                for (int j = 0; j < CPT; ++j) {
                    const int ox = x0 + CPT * t + j;
                    if (ox < OW) {
                        const float mu1 = V[j][0], mu2 = V[j][1];
                        const float m11 = mu1 * mu1;
                        const float m22 = mu2 * mu2;
                        const float m12 = mu1 * mu2;
                        const float sg1  = V[j][2] - m11;
                        const float sg2  = V[j][3] - m22;
                        const float sg12 = V[j][4] - m12;
                        const float num = (2.0f * m12 + C1f) * (2.0f * sg12 + C2f);
                        const float den = (m11 + m22 + C1f) * (sg1 + sg2 + C2f);
                        acc += 1.0f - num / den;
                    }
                }
            }

            // ---- publish prefetched row into the other buffer ----
            const int nxt = cur ^ 1;
            sma[nxt][lc0] = pa0;  smb[nxt][lc0] = pb0;
            sma[nxt][lc1] = pa1;  smb[nxt][lc1] = pb1;
            if (has2) { sma[nxt][lc2] = pa2; smb[nxt][lc2] = pb2; }
            __syncthreads();
        }
    }

    // ---- reduction: warp shuffle -> smem -> one double atomic per CTA ----
#pragma unroll
    for (int o = 16; o; o >>= 1) acc += __shfl_xor_sync(FULLMASK, acc, o);
    if ((t & 31) == 0) wsum[t >> 5] = acc;
    __syncthreads();
    if (t == 0) {
        const double s = (double)wsum[0] + (double)wsum[1] +
                         (double)wsum[2] + (double)wsum[3];
        atomicAdd(&g_acc, s);
    }
}

extern "C" void kernel_launch(void* const* d_in, const int* in_sizes, int n_in,
                              void* d_out, int out_size)
{
    const float* A = (const float*)d_in[0];   // groundtruth
    const float* B = (const float*)d_in[1];   // noisy_img
    float* out = (float*)d_out;

    zero_acc_kernel<<<1, 1>>>();
    dim3 grid(2, NB, NIMG);                    // col-tiles x bands x images
    ssim_kernel<<<grid, THREADS>>>(A, B);
    finalize_kernel<<<1, 1>>>(out);
}